// round 16
// baseline (speedup 1.0000x reference)
#include <cuda_runtime.h>
#include <cstdint>
#include <math.h>

#define D 512
#define K 5
#define THREADS 224   // 7 warps/block, 2 blocks/SM -> reg cap 146
#define BLOCKS 296    // persistent: 2 blocks/SM * 148

typedef unsigned long long ull;

__device__ __forceinline__ ull pack2(float lo, float hi) {
    ull r;
    asm("mov.b64 %0, {%1, %2};" : "=l"(r) : "f"(lo), "f"(hi));
    return r;
}
__device__ __forceinline__ void unpack2(ull v, float& lo, float& hi) {
    asm("mov.b64 {%0, %1}, %2;" : "=f"(lo), "=f"(hi) : "l"(v));
}
__device__ __forceinline__ ull fma2(ull a, ull b, ull c) {
    ull d;
    asm("fma.rn.f32x2 %0, %1, %2, %3;" : "=l"(d) : "l"(a), "l"(b), "l"(c));
    return d;
}
__device__ __forceinline__ ull mul2(ull a, ull b) {
    ull d;
    asm("mul.rn.f32x2 %0, %1, %2;" : "=l"(d) : "l"(a), "l"(b));
    return d;
}
__device__ __forceinline__ void load_row(ull v[8], const float* x, int row, int lane) {
    const ull* xr = reinterpret_cast<const ull*>(x + (size_t)row * D);
    #pragma unroll
    for (int p = 0; p < 8; p++) v[p] = xr[2 * lane + ((p >> 1) << 6) + (p & 1)];
}

// Tail for one row: butterfly reduce -> softmax -> mapping/pred -> rec store.
__device__ __forceinline__ void row_tail(
    int row, ull acc[K], const ull (&w2)[K][8],
    const float* s_swr, const float4* rinv4, int lane,
    float* __restrict__ out_map, float* __restrict__ out_rec,
    float* __restrict__ out_pred)
{
    float dist[K];
    #pragma unroll
    for (int k = 0; k < K; k++) {
        float lo, hi;
        unpack2(acc[k], lo, hi);
        dist[k] = lo + hi;
    }
    // Interleaved butterfly: 'off' outer so the 5 chains overlap
    #pragma unroll
    for (int off = 16; off > 0; off >>= 1) {
        #pragma unroll
        for (int k = 0; k < K; k++)
            dist[k] += __shfl_xor_sync(0xffffffffu, dist[k], off);
    }

    // Softmax over K=5 (replicated in all lanes)
    float m = dist[0];
    #pragma unroll
    for (int k = 1; k < K; k++) m = fmaxf(m, dist[k]);
    float mp[K];
    float s = 0.0f;
    #pragma unroll
    for (int k = 0; k < K; k++) { mp[k] = __expf(dist[k] - m); s += mp[k]; }
    const float inv = 1.0f / s;
    #pragma unroll
    for (int k = 0; k < K; k++) mp[k] *= inv;

    if (lane < K) out_map[(size_t)row * K + lane] = mp[lane];
    if (lane == 0) {
        float p = 0.0f;
        #pragma unroll
        for (int k = 0; k < K; k++) p += mp[k] * s_swr[k];
        out_pred[row] = p;
    }

    // Reconstruction: rec_d = rinv_d * sum_k mp_k * w_kd
    ull mp2[K];
    #pragma unroll
    for (int k = 0; k < K; k++) mp2[k] = pack2(mp[k], mp[k]);

    float4* orow = reinterpret_cast<float4*>(out_rec + (size_t)row * D);
    #pragma unroll
    for (int j = 0; j < 4; j++) {
        ull sa = mul2(mp2[0], w2[0][2 * j]);
        ull sb = mul2(mp2[0], w2[0][2 * j + 1]);
        #pragma unroll
        for (int k = 1; k < K; k++) {
            sa = fma2(mp2[k], w2[k][2 * j], sa);
            sb = fma2(mp2[k], w2[k][2 * j + 1], sb);
        }
        const float4 rv = rinv4[lane + j * 32];
        float4 o;
        float t0, t1;
        unpack2(sa, t0, t1);
        o.x = t0 * rv.x; o.y = t1 * rv.y;
        unpack2(sb, t0, t1);
        o.z = t0 * rv.z; o.w = t1 * rv.w;
        orow[lane + j * 32] = o;
    }
}

// ---------------------------------------------------------------------------
// Fully fused kernel, DEPTH-2 register prefetch (double-buffered v2a/v2b).
//   dist_k = x . w_k + pc2_k  (w = -2*alpha*c in regs; alpha*x^2 cancels)
//   rec_d  = rinv_d * sum_k mp_k * w_kd     (rinv = -0.5/alpha, shared)
//   pred   = sum_k mp_k * sigmoid(cw_k)
// Loads for row r+2S issue right after row r's fma stage consumes its
// buffer, giving each load ~2 full row-tails (>800 cyc) to land.
//   v2[p] = xr[2*lane + 64*(p>>1) + (p&1)]  pairs with  w2[k][p].
// ---------------------------------------------------------------------------
__global__ __launch_bounds__(THREADS, 2) void lfr_fused(
    const float* __restrict__ x,          // (N, D)
    const float* __restrict__ alpha,      // (D,)
    const float* __restrict__ cw,         // (K,)
    const float* __restrict__ cent,       // (K, D)
    float* __restrict__ out_map,          // (N, K)
    float* __restrict__ out_rec,          // (N, D)
    float* __restrict__ out_pred,         // (N,)
    int n_rows)
{
    __shared__ float s_rinv[D];           // -0.5 / alpha_d
    __shared__ float s_swr[K];            // sigmoid(cw_k)

    const int tid  = threadIdx.x;
    const int lane = tid & 31;

    for (int i = tid; i < D; i += THREADS) s_rinv[i] = -0.5f / alpha[i];
    if (tid < K) s_swr[tid] = 1.0f / (1.0f + __expf(-cw[tid]));

    // ---- per-lane invariant setup: packed weights + c2 partials ----
    ull  w2[K][8];      // packed -2*alpha*c  (80 regs)
    float pc2[K];       // per-lane partial of sum(alpha*c^2)
    {
        float4 a4[4];
        #pragma unroll
        for (int j = 0; j < 4; j++)
            a4[j] = reinterpret_cast<const float4*>(alpha)[lane + j * 32];
        #pragma unroll
        for (int k = 0; k < K; k++) {
            pc2[k] = 0.0f;
            const float4* ck = reinterpret_cast<const float4*>(cent + k * D);
            #pragma unroll
            for (int j = 0; j < 4; j++) {
                const float4 c = ck[lane + j * 32];
                pc2[k] += a4[j].x * c.x * c.x + a4[j].y * c.y * c.y
                        + a4[j].z * c.z * c.z + a4[j].w * c.w * c.w;
                w2[k][2 * j]     = pack2(-2.0f * a4[j].x * c.x, -2.0f * a4[j].y * c.y);
                w2[k][2 * j + 1] = pack2(-2.0f * a4[j].z * c.z, -2.0f * a4[j].w * c.w);
            }
        }
    }
    __syncthreads();

    const int warp_global = (blockIdx.x * THREADS + tid) >> 5;
    const int S           = (BLOCKS * THREADS) >> 5;   // 2072 warps
    const float4* rinv4   = reinterpret_cast<const float4*>(s_rinv);

    // Prime: rows r and r+S into the two buffers
    ull v2a[8], v2b[8];
    int rowA = warp_global;
    if (rowA < n_rows)     load_row(v2a, x, rowA, lane);
    if (rowA + S < n_rows) load_row(v2b, x, rowA + S, lane);

    while (rowA < n_rows) {
        // ---- phase A: consume v2a, refill with rowA+2S ----
        ull acc[K];
        #pragma unroll
        for (int k = 0; k < K; k++) acc[k] = pack2(pc2[k], 0.0f);
        #pragma unroll
        for (int p = 0; p < 8; p++) {
            #pragma unroll
            for (int k = 0; k < K; k++)
                acc[k] = fma2(v2a[p], w2[k][p], acc[k]);
        }
        if (rowA + 2 * S < n_rows) load_row(v2a, x, rowA + 2 * S, lane);

        row_tail(rowA, acc, w2, s_swr, rinv4, lane, out_map, out_rec, out_pred);

        // ---- phase B: consume v2b, refill with rowB+2S ----
        const int rowB = rowA + S;
        if (rowB < n_rows) {
            #pragma unroll
            for (int k = 0; k < K; k++) acc[k] = pack2(pc2[k], 0.0f);
            #pragma unroll
            for (int p = 0; p < 8; p++) {
                #pragma unroll
                for (int k = 0; k < K; k++)
                    acc[k] = fma2(v2b[p], w2[k][p], acc[k]);
            }
            if (rowB + 2 * S < n_rows) load_row(v2b, x, rowB + 2 * S, lane);

            row_tail(rowB, acc, w2, s_swr, rinv4, lane, out_map, out_rec, out_pred);
        }

        rowA += 2 * S;
    }
}

extern "C" void kernel_launch(void* const* d_in, const int* in_sizes, int n_in,
                              void* d_out, int out_size) {
    // metadata order: x, is_protected (unused), alpha_p, classif_w, centroids
    const float* x     = (const float*)d_in[0];
    const float* alpha = (const float*)d_in[2];
    const float* w     = (const float*)d_in[3];
    const float* cent  = (const float*)d_in[4];

    const int n_rows = in_sizes[0] / D;   // 65536

    float* out      = (float*)d_out;
    float* out_map  = out;                              // N*K
    float* out_rec  = out + (size_t)n_rows * K;         // N*D
    float* out_pred = out_rec + (size_t)n_rows * D;     // N

    lfr_fused<<<BLOCKS, THREADS>>>(x, alpha, w, cent, out_map, out_rec, out_pred, n_rows);
}

// round 17
// speedup vs baseline: 1.5418x; 1.5418x over previous
#include <cuda_runtime.h>
#include <cstdint>
#include <math.h>

#define D 512
#define K 5
#define THREADS 192   // 6 warps/block, 2 blocks/SM -> reg cap 170 (R13-proven)
#define BLOCKS 296    // persistent: 2 blocks/SM * 148

typedef unsigned long long ull;

__device__ __forceinline__ ull pack2(float lo, float hi) {
    ull r;
    asm("mov.b64 %0, {%1, %2};" : "=l"(r) : "f"(lo), "f"(hi));
    return r;
}
__device__ __forceinline__ void unpack2(ull v, float& lo, float& hi) {
    asm("mov.b64 {%0, %1}, %2;" : "=f"(lo), "=f"(hi) : "l"(v));
}
__device__ __forceinline__ ull fma2(ull a, ull b, ull c) {
    ull d;
    asm("fma.rn.f32x2 %0, %1, %2, %3;" : "=l"(d) : "l"(a), "l"(b), "l"(c));
    return d;
}
__device__ __forceinline__ ull mul2(ull a, ull b) {
    ull d;
    asm("mul.rn.f32x2 %0, %1, %2;" : "=l"(d) : "l"(a), "l"(b));
    return d;
}
__device__ __forceinline__ void load_row(ull v[8], const float* x, int row, int lane) {
    const ull* xr = reinterpret_cast<const ull*>(x + (size_t)row * D);
    #pragma unroll
    for (int p = 0; p < 8; p++) v[p] = xr[2 * lane + ((p >> 1) << 6) + (p & 1)];
}

// Tail for one row: butterfly reduce -> softmax -> mapping/pred -> rec store.
__device__ __forceinline__ void row_tail(
    int row, ull acc[K], const ull (&w2)[K][8],
    const float* s_swr, const float4* rinv4, int lane,
    float* __restrict__ out_map, float* __restrict__ out_rec,
    float* __restrict__ out_pred)
{
    float dist[K];
    #pragma unroll
    for (int k = 0; k < K; k++) {
        float lo, hi;
        unpack2(acc[k], lo, hi);
        dist[k] = lo + hi;
    }
    // Interleaved butterfly: 'off' outer so the 5 chains overlap
    #pragma unroll
    for (int off = 16; off > 0; off >>= 1) {
        #pragma unroll
        for (int k = 0; k < K; k++)
            dist[k] += __shfl_xor_sync(0xffffffffu, dist[k], off);
    }

    // Softmax over K=5 (replicated in all lanes)
    float m = dist[0];
    #pragma unroll
    for (int k = 1; k < K; k++) m = fmaxf(m, dist[k]);
    float mp[K];
    float s = 0.0f;
    #pragma unroll
    for (int k = 0; k < K; k++) { mp[k] = __expf(dist[k] - m); s += mp[k]; }
    const float inv = 1.0f / s;
    #pragma unroll
    for (int k = 0; k < K; k++) mp[k] *= inv;

    if (lane < K) out_map[(size_t)row * K + lane] = mp[lane];
    if (lane == 0) {
        float p = 0.0f;
        #pragma unroll
        for (int k = 0; k < K; k++) p += mp[k] * s_swr[k];
        out_pred[row] = p;
    }

    // Reconstruction: rec_d = rinv_d * sum_k mp_k * w_kd
    ull mp2[K];
    #pragma unroll
    for (int k = 0; k < K; k++) mp2[k] = pack2(mp[k], mp[k]);

    float4* orow = reinterpret_cast<float4*>(out_rec + (size_t)row * D);
    #pragma unroll
    for (int j = 0; j < 4; j++) {
        ull sa = mul2(mp2[0], w2[0][2 * j]);
        ull sb = mul2(mp2[0], w2[0][2 * j + 1]);
        #pragma unroll
        for (int k = 1; k < K; k++) {
            sa = fma2(mp2[k], w2[k][2 * j], sa);
            sb = fma2(mp2[k], w2[k][2 * j + 1], sb);
        }
        const float4 rv = rinv4[lane + j * 32];
        float4 o;
        float t0, t1;
        unpack2(sa, t0, t1);
        o.x = t0 * rv.x; o.y = t1 * rv.y;
        unpack2(sb, t0, t1);
        o.z = t0 * rv.z; o.w = t1 * rv.w;
        orow[lane + j * 32] = o;
    }
}

// ---------------------------------------------------------------------------
// Fully fused kernel, DEPTH-2 register prefetch (double-buffered v2a/v2b)
// at a block shape whose 170-reg cap actually fits both buffers (the 224-thr
// variant spilled: ncu showed regs=128 + DRAM 41% -> local-memory thrash).
//   dist_k = x . w_k + pc2_k  (w = -2*alpha*c in regs; alpha*x^2 cancels)
//   rec_d  = rinv_d * sum_k mp_k * w_kd     (rinv = -0.5/alpha, shared)
//   pred   = sum_k mp_k * sigmoid(cw_k)
// Loads for row r+2S issue right after row r's fma stage consumes its
// buffer, giving each load ~2 full row-tails (>800 cyc) to land.
//   v2[p] = xr[2*lane + 64*(p>>1) + (p&1)]  pairs with  w2[k][p].
// ---------------------------------------------------------------------------
__global__ __launch_bounds__(THREADS, 2) void lfr_fused(
    const float* __restrict__ x,          // (N, D)
    const float* __restrict__ alpha,      // (D,)
    const float* __restrict__ cw,         // (K,)
    const float* __restrict__ cent,       // (K, D)
    float* __restrict__ out_map,          // (N, K)
    float* __restrict__ out_rec,          // (N, D)
    float* __restrict__ out_pred,         // (N,)
    int n_rows)
{
    __shared__ float s_rinv[D];           // -0.5 / alpha_d
    __shared__ float s_swr[K];            // sigmoid(cw_k)

    const int tid  = threadIdx.x;
    const int lane = tid & 31;

    for (int i = tid; i < D; i += THREADS) s_rinv[i] = -0.5f / alpha[i];
    if (tid < K) s_swr[tid] = 1.0f / (1.0f + __expf(-cw[tid]));

    // ---- per-lane invariant setup: packed weights + c2 partials ----
    ull  w2[K][8];      // packed -2*alpha*c  (80 regs)
    float pc2[K];       // per-lane partial of sum(alpha*c^2)
    {
        float4 a4[4];
        #pragma unroll
        for (int j = 0; j < 4; j++)
            a4[j] = reinterpret_cast<const float4*>(alpha)[lane + j * 32];
        #pragma unroll
        for (int k = 0; k < K; k++) {
            pc2[k] = 0.0f;
            const float4* ck = reinterpret_cast<const float4*>(cent + k * D);
            #pragma unroll
            for (int j = 0; j < 4; j++) {
                const float4 c = ck[lane + j * 32];
                pc2[k] += a4[j].x * c.x * c.x + a4[j].y * c.y * c.y
                        + a4[j].z * c.z * c.z + a4[j].w * c.w * c.w;
                w2[k][2 * j]     = pack2(-2.0f * a4[j].x * c.x, -2.0f * a4[j].y * c.y);
                w2[k][2 * j + 1] = pack2(-2.0f * a4[j].z * c.z, -2.0f * a4[j].w * c.w);
            }
        }
    }
    __syncthreads();

    const int warp_global = (blockIdx.x * THREADS + tid) >> 5;
    const int S           = (BLOCKS * THREADS) >> 5;   // 1776 warps
    const float4* rinv4   = reinterpret_cast<const float4*>(s_rinv);

    // Prime: rows r and r+S into the two buffers
    ull v2a[8], v2b[8];
    int rowA = warp_global;
    if (rowA < n_rows)     load_row(v2a, x, rowA, lane);
    if (rowA + S < n_rows) load_row(v2b, x, rowA + S, lane);

    while (rowA < n_rows) {
        // ---- phase A: consume v2a, refill with rowA+2S ----
        ull acc[K];
        #pragma unroll
        for (int k = 0; k < K; k++) acc[k] = pack2(pc2[k], 0.0f);
        #pragma unroll
        for (int p = 0; p < 8; p++) {
            #pragma unroll
            for (int k = 0; k < K; k++)
                acc[k] = fma2(v2a[p], w2[k][p], acc[k]);
        }
        if (rowA + 2 * S < n_rows) load_row(v2a, x, rowA + 2 * S, lane);

        row_tail(rowA, acc, w2, s_swr, rinv4, lane, out_map, out_rec, out_pred);

        // ---- phase B: consume v2b, refill with rowB+2S ----
        const int rowB = rowA + S;
        if (rowB < n_rows) {
            #pragma unroll
            for (int k = 0; k < K; k++) acc[k] = pack2(pc2[k], 0.0f);
            #pragma unroll
            for (int p = 0; p < 8; p++) {
                #pragma unroll
                for (int k = 0; k < K; k++)
                    acc[k] = fma2(v2b[p], w2[k][p], acc[k]);
            }
            if (rowB + 2 * S < n_rows) load_row(v2b, x, rowB + 2 * S, lane);

            row_tail(rowB, acc, w2, s_swr, rinv4, lane, out_map, out_rec, out_pred);
        }

        rowA += 2 * S;
    }
}

extern "C" void kernel_launch(void* const* d_in, const int* in_sizes, int n_in,
                              void* d_out, int out_size) {
    // metadata order: x, is_protected (unused), alpha_p, classif_w, centroids
    const float* x     = (const float*)d_in[0];
    const float* alpha = (const float*)d_in[2];
    const float* w     = (const float*)d_in[3];
    const float* cent  = (const float*)d_in[4];

    const int n_rows = in_sizes[0] / D;   // 65536

    float* out      = (float*)d_out;
    float* out_map  = out;                              // N*K
    float* out_rec  = out + (size_t)n_rows * K;         // N*D
    float* out_pred = out_rec + (size_t)n_rows * D;     // N

    lfr_fused<<<BLOCKS, THREADS>>>(x, alpha, w, cent, out_map, out_rec, out_pred, n_rows);
}